// round 16
// baseline (speedup 1.0000x reference)
#include <cuda_runtime.h>
#include <cuda_fp16.h>
#include <math.h>
#include <stdint.h>

// ---------------------------------------------------------------------------
// IIDSegmentationLoss on GB300 — Round 13: 3-stage pipeline, 1 sync/iter
//
// p[dy,dx,i,j] = sum_{n,y,k} A[n,i,y+dy-7,x0+k] * B[n,j,y,x0+k+7-dx]
//   GEMM per K-block (n, y0, 112-wide x-chunk):
//     M = 80  : (i 0..4)*16 + dy      N = 152 : (dx)*10 + j (+2 pad)
//     K = 112 : 7 k-steps of 16
//   B stored twice in global (padded + one-element-shifted copy) so every
//   dx shift yields 4B-aligned fp16 pairs in smem.
// ---------------------------------------------------------------------------

#define Tn      15
#define Kc      10
#define Hh      224
#define Ww      224
#define NBINS   (Tn*Tn*Kc*Kc)        // 22500
#define NELEM   (16*Kc*Hh*Ww)        // 8,028,160
#define BPW     240                  // padded B row width (x = -8 .. 231)
#define NBELEM  (16*Kc*Hh*BPW)
#define XCH     2                    // x-chunks of 112 (exact)
#define KCH     112
#define NBLK    (16*Hh*XCH)          // 7168 K-blocks per i-half
#define NCTA    148                  // grid.x (x2 i-halves = 296 CTAs, 2/SM)
#define APITCHW 60                   // A row pitch in words (112 fp16 + pad)
#define AWORDS  (80*APITCHW)         // 4800
#define BPITCHW 68                   // B row pitch in words (64 + pad)
#define CB0     AWORDS               // copy0 base word
#define CB1     (AWORDS + Kc*BPITCHW)   // 5480
#define SWORDS  6176                 // stage words (5480+680=6160, pad)
#define NST     3                    // pipeline stages
#define SMEM_DYN (NST*SWORDS*4)      // 74112 bytes (x2 CTA = 148KB <= 228KB)
#define NNT     19                   // n8 tiles (152 cols, 150 valid)

typedef uint32_t u32;

__device__ float g_p[NBINS];
__device__ unsigned g_min_bits;
__device__ __half g_Ah[NELEM];       // fp16 A, plain [160][224][224]
__device__ __half g_Bp[NBELEM];      // fp16 B, padded [160][224][240], x at xp-8
__device__ __half g_Bp2[NBELEM];     // shifted copy: x at xp-7

// ---------------- baseline PTX helpers ----------------
__device__ __forceinline__ u32 smem_u32(const void* p) {
    u32 a;
    asm("{ .reg .u64 t; cvta.to.shared.u64 t, %1; cvt.u32.u64 %0, t; }"
        : "=r"(a) : "l"(p));
    return a;
}

__device__ __forceinline__ u32 h2_bits(__half2 h) {
    return *reinterpret_cast<u32*>(&h);
}

#define CP_ASYNC16(dst, src, sz) \
    asm volatile("cp.async.cg.shared.global [%0], [%1], 16, %2;" \
                 :: "r"(dst), "l"(src), "r"(sz) : "memory")
#define CP_COMMIT() asm volatile("cp.async.commit_group;" ::: "memory")
#define CP_WAIT(N)  asm volatile("cp.async.wait_group %0;" :: "n"(N) : "memory")

#define MMA_F16(d, a0, a1, a2, a3, b0, b1)                                     \
    asm volatile("mma.sync.aligned.m16n8k16.row.col.f32.f16.f16.f32 "         \
        "{%0,%1,%2,%3},{%4,%5,%6,%7},{%8,%9},{%0,%1,%2,%3};"                   \
        : "+f"((d)[0]), "+f"((d)[1]), "+f"((d)[2]), "+f"((d)[3])               \
        : "r"(a0), "r"(a1), "r"(a2), "r"(a3), "r"(b0), "r"(b1))

// ---------------------------------------------------------------------------
// fp32 -> fp16 into A (plain) and B (padded + shifted copies); also zeros g_p.
__global__ void convert_kernel(const float* __restrict__ A,
                               const float* __restrict__ B,
                               float* __restrict__ out) {
    const int gt = blockIdx.x * blockDim.x + threadIdx.x;
    if (gt < NBINS) g_p[gt] = 0.0f;
    if (gt == 0) { out[0] = 0.0f; g_min_bits = 0x7f7fffffu; }

    int i4 = gt * 4;
    if (i4 + 3 >= NELEM) return;
    float4 a = *(const float4*)(A + i4);
    float4 b = *(const float4*)(B + i4);
    __half2 a01 = __floats2half2_rn(a.x, a.y);
    __half2 a23 = __floats2half2_rn(a.z, a.w);
    __half2 b01 = __floats2half2_rn(b.x, b.y);
    __half2 b23 = __floats2half2_rn(b.z, b.w);
    *(uint2*)(g_Ah + i4) = make_uint2(h2_bits(a01), h2_bits(a23));
    int ch = i4 / (Hh * Ww);
    int r  = i4 - ch * (Hh * Ww);
    int y  = r / Ww;
    int x  = r - y * Ww;                     // multiple of 4
    size_t rb = ((size_t)ch * Hh + y) * BPW;
    *(uint2*)(g_Bp + rb + x + 8) = make_uint2(h2_bits(b01), h2_bits(b23));
    __half* p2 = g_Bp2 + rb + x + 7;
    p2[0] = __low2half(b01);  p2[1] = __high2half(b01);
    p2[2] = __low2half(b23);  p2[3] = __high2half(b23);
}

// ---------------------------------------------------------------------------
// Stage one K-block (n, y0, x0) into smem slot s. All 16B aligned cp.async.
// ---------------------------------------------------------------------------
__device__ __forceinline__ void stage_load(u32 smbase, int s, int blk,
                                           int ih, int tid)
{
    const int n  = blk / (Hh * XCH);
    const int r  = blk - n * (Hh * XCH);
    const int y0 = r >> 1;
    const int x0 = (r & 1) * KCH;
    const u32 st = smbase + (u32)s * (SWORDS * 4);

    // A: 5*16*14 = 1120 16B ops
    #pragma unroll
    for (int q = 0; q < 5; ++q) {
        const int idx = tid + q * 256;
        if (idx < 1120) {
            const int i   = idx / 224;
            const int rem = idx - i * 224;
            const int rr  = rem / 14;
            const int c   = rem - rr * 14;
            const int gy  = y0 - 7 + rr;
            const u32 dst = st + (u32)((i * 16 + rr) * APITCHW + c * 4) * 4u;
            const bool ok = (gy >= 0) && (gy < Hh);
            const __half* src = ok
                ? g_Ah + ((size_t)((n * Kc) + ih * 5 + i) * Hh + gy) * Ww + x0 + c * 8
                : g_Ah;
            CP_ASYNC16(dst, src, ok ? 16u : 0u);
        }
    }
    // B: 2 copies x 10 ch x 16 16B ops = 320 ops
    #pragma unroll
    for (int q = 0; q < 2; ++q) {
        const int id2 = tid + q * 256;
        if (id2 < 320) {
            const int cp = (id2 >> 4) >= Kc ? 1 : 0;
            const int jj = (id2 >> 4) - cp * Kc;
            const int c  = id2 & 15;
            const __half* gsrc = (cp ? g_Bp2 : g_Bp)
                + ((size_t)(n * Kc + jj) * Hh + y0) * BPW + x0 + c * 8;
            const u32 dst = st
                + (u32)((cp ? CB1 : CB0) + jj * BPITCHW + c * 4) * 4u;
            CP_ASYNC16(dst, gsrc, 16u);
        }
    }
}

// ---------------------------------------------------------------------------
// grid = (148, 2 i-halves), 256 threads, 2 CTAs/SM, 3-stage pipeline.
// ---------------------------------------------------------------------------
__global__ void __launch_bounds__(256, 2) corr_kernel()
{
    extern __shared__ u32 sm[];
    const u32 smbase = smem_u32(sm);
    const int tid  = threadIdx.x;
    const int ih   = blockIdx.y;
    const int bx   = blockIdx.x;
    const int w    = tid >> 5;
    const int lane = tid & 31;
    const int g    = lane >> 2;
    const int t    = lane & 3;

    const int lo = (int)(((long long)bx * NBLK) / NCTA);
    const int hi = (int)(((long long)(bx + 1) * NBLK) / NCTA);

    const int wg   = w >> 2;          // m-group: 0 -> tiles 0-2, 1 -> 3-4
    const int wn   = w & 3;           // n-quarter
    const int mcnt = wg == 0 ? 3 : 2;

    int ntv[5];
    #pragma unroll
    for (int u = 0; u < 5; ++u) ntv[u] = wn * 5 + u;

    int aoff[3];
    #pragma unroll
    for (int m = 0; m < 3; ++m)
        aoff[m] = ((wg * 3 + m) * 16 + g) * APITCHW;

    int boff[5];
    #pragma unroll
    for (int u = 0; u < 5; ++u) {
        int n = ntv[u] * 8 + g;
        if (n > 149) n = 149;
        const int dxb = n / Kc, jb = n - dxb * Kc;
        const int s15 = 15 - dxb;                       // 1..15
        boff[u] = (s15 & 1)
            ? CB1 + jb * BPITCHW + ((s15 - 1) >> 1)     // odd  -> shifted copy
            : CB0 + jb * BPITCHW + (s15 >> 1);          // even -> aligned copy
    }

    float d[3][5][4];
    #pragma unroll
    for (int m = 0; m < 3; ++m)
        #pragma unroll
        for (int u = 0; u < 5; ++u)
            #pragma unroll
            for (int e = 0; e < 4; ++e) d[m][u][e] = 0.0f;

    // ---- prologue: stage slots 0 and 1 ----
    stage_load(smbase, 0, lo, ih, tid);
    CP_COMMIT();
    if (lo + 1 < hi) stage_load(smbase, 1, lo + 1, ih, tid);
    CP_COMMIT();

    int cur = 0;
    for (int blk = lo; blk < hi; ++blk) {
        CP_WAIT(1);                   // slot cur landed (per-thread)
        __syncthreads();              // all threads' cur data visible;
                                      // also: everyone done computing blk-1
        // stage blk+2 into slot (cur+2)%3 (last read at iter blk-1)
        if (blk + 2 < hi) {
            int s2 = cur + 2; if (s2 >= NST) s2 -= NST;
            stage_load(smbase, s2, blk + 2, ih, tid);
        }
        CP_COMMIT();                  // unconditional: keeps group counts exact

        const u32* sc = sm + cur * SWORDS;
        #pragma unroll
        for (int ks = 0; ks < 7; ++ks) {
            const int kw = ks * 8;
            u32 bf[5][2];
            #pragma unroll
            for (int u = 0; u < 5; ++u) {
                if (ntv[u] < NNT) {
                    bf[u][0] = sc[boff[u] + kw + t];
                    bf[u][1] = sc[boff[u] + kw + t + 4];
                }
            }
            #pragma unroll
            for (int m = 0; m < 3; ++m) {
                if (m < mcnt) {
                    const u32 a0 = sc[aoff[m] + kw + t];
                    const u32 a1 = sc[aoff[m] + 8 * APITCHW + kw + t];
                    const u32 a2 = sc[aoff[m] + kw + t + 4];
                    const u32 a3 = sc[aoff[m] + 8 * APITCHW + kw + t + 4];
                    #pragma unroll
                    for (int u = 0; u < 5; ++u)
                        if (ntv[u] < NNT)
                            MMA_F16(d[m][u], a0, a1, a2, a3, bf[u][0], bf[u][1]);
                }
            }
        }
        if (++cur == NST) cur = 0;
    }

    // ---- epilogue: atomic fold into g_p ----
    #pragma unroll
    for (int m = 0; m < 3; ++m) {
        if (m >= mcnt) continue;
        const int ig = ih * 5 + wg * 3 + m;
        #pragma unroll
        for (int u = 0; u < 5; ++u) {
            if (ntv[u] >= NNT) continue;
            #pragma unroll
            for (int e = 0; e < 4; ++e) {
                const int dy = g + (e >> 1) * 8;
                const int nn = ntv[u] * 8 + 2 * t + (e & 1);
                if (dy < Tn && nn < Tn * Kc) {
                    const int dx = nn / Kc;
                    const int j  = nn - dx * Kc;
                    atomicAdd(&g_p[((dy * Tn + dx) * Kc + ig) * Kc + j],
                              d[m][u][e]);
                }
            }
        }
    }
}

// ---------------------------------------------------------------------------
// min (parallel, atomicMin on positive-float bits) + per-shift loss.
// ---------------------------------------------------------------------------
__global__ void min_kernel() {
    __shared__ float red[256];
    const int tid = threadIdx.x;
    const int idx = blockIdx.x * 256 + tid;
    float m = (idx < NBINS) ? g_p[idx] : 3.402823466e38f;
    red[tid] = m;
    __syncthreads();
    for (int s = 128; s > 0; s >>= 1) {
        if (tid < s) red[tid] = fminf(red[tid], red[tid + s]);
        __syncthreads();
    }
    if (tid == 0) atomicMin(&g_min_bits, __float_as_uint(red[0]));
}

__global__ void loss_kernel(float* __restrict__ out) {
    __shared__ float sv[100];
    __shared__ float ss[100];
    __shared__ float red[128];
    const int t   = blockIdx.x;          // shift 0..224
    const int tid = threadIdx.x;         // 0..127
    const float m = __uint_as_float(g_min_bits);

    float v = 0.0f;
    if (tid < 100) {
        v = g_p[t * 100 + tid] - m + 1e-16f;
        sv[tid] = v;
    }
    red[tid] = (tid < 100) ? v : 0.0f;
    __syncthreads();
    for (int s = 64; s > 0; s >>= 1) {
        if (tid < s) red[tid] += red[tid + s];
        __syncthreads();
    }
    const float inv = 1.0f / red[0];
    __syncthreads();

    const int i = tid / 10, j = tid - (tid / 10) * 10;
    float sym = 0.0f;
    if (tid < 100) {
        sym = (i == j) ? v * inv : 0.5f * (v + sv[j * 10 + i]) * inv;
        ss[tid] = sym;
    }
    __syncthreads();

    float l = 0.0f;
    if (tid < 100) {
        float pi = 0.0f, pj = 0.0f;
        #pragma unroll
        for (int q = 0; q < 10; ++q) {
            pi += ss[q * 10 + j];
            pj += ss[i * 10 + q];
        }
        l = -sym * (logf(sym + 1e-16f) - logf(pi + 1e-16f) - logf(pj + 1e-16f));
    }
    red[tid] = l;
    __syncthreads();
    for (int s = 64; s > 0; s >>= 1) {
        if (tid < s) red[tid] += red[tid + s];
        __syncthreads();
    }
    if (tid == 0) atomicAdd(out, red[0] * (1.0f / (Tn * Tn)));
}

// ---------------------------------------------------------------------------
extern "C" void kernel_launch(void* const* d_in, const int* in_sizes, int n_in,
                              void* d_out, int out_size)
{
    (void)in_sizes; (void)n_in; (void)out_size;
    const float* A = (const float*)d_in[0];   // x_out    (16,10,224,224) f32
    const float* B = (const float*)d_in[1];   // x_tf_out (16,10,224,224) f32
    float* out = (float*)d_out;

    cudaFuncSetAttribute(corr_kernel,
                         cudaFuncAttributeMaxDynamicSharedMemorySize, SMEM_DYN);

    convert_kernel<<<NELEM / 4 / 256, 256>>>(A, B, out);
    corr_kernel<<<dim3(NCTA, 2), 256, SMEM_DYN>>>();
    min_kernel<<<(NBINS + 255) / 256, 256>>>();
    loss_kernel<<<Tn * Tn, 128>>>(out);
}